// round 14
// baseline (speedup 1.0000x reference)
#include <cuda_runtime.h>
#include <cuda_bf16.h>
#include <cstdint>
#include <math.h>

#define BB 8
#define NN 2048
#define DD 768

typedef __nv_bfloat16 bf16;

// ---------------- scratch (no allocation allowed) ----------------
__device__ bf16  g_G2h[BB * NN * DD];   // exp(x2)/sqrt(rowsum)
__device__ bf16  g_G3h[BB * NN * DD];
__device__ float g_sr2[BB * NN];        // sqrt(rowsum(exp(x2)))
__device__ float g_sr3[BB * NN];
__device__ float g_c2i[BB * DD];        // 1 / colsum(exp(x2))
__device__ float g_c3i[BB * DD];
__device__ bf16  g_S1h[BB * DD * DD];
__device__ bf16  g_S2h[BB * DD * DD];
__device__ bf16  g_MTh[BB * DD * DD];
__device__ bf16  g_Wh [2 * DD * DD];
__device__ bf16  g_xh [BB * NN * DD];

// ---------------- helpers ----------------
__device__ __forceinline__ uint32_t smem_u32(const void* p) {
    uint32_t a;
    asm("{ .reg .u64 t; cvta.to.shared.u64 t, %1; cvt.u32.u64 %0, t; }" : "=r"(a) : "l"(p));
    return a;
}
__device__ __forceinline__ void ldsm4(uint32_t* r, uint32_t addr) {
    asm volatile("ldmatrix.sync.aligned.m8n8.x4.shared.b16 {%0,%1,%2,%3}, [%4];"
        : "=r"(r[0]), "=r"(r[1]), "=r"(r[2]), "=r"(r[3]) : "r"(addr));
}
__device__ __forceinline__ void ldsm4t(uint32_t* r, uint32_t addr) {
    asm volatile("ldmatrix.sync.aligned.m8n8.x4.trans.shared.b16 {%0,%1,%2,%3}, [%4];"
        : "=r"(r[0]), "=r"(r[1]), "=r"(r[2]), "=r"(r[3]) : "r"(addr));
}
__device__ __forceinline__ void mma16816(float* d, const uint32_t* a, const uint32_t* b) {
    asm volatile("mma.sync.aligned.m16n8k16.row.col.f32.bf16.bf16.f32 "
        "{%0,%1,%2,%3}, {%4,%5,%6,%7}, {%8,%9}, {%0,%1,%2,%3};"
        : "+f"(d[0]), "+f"(d[1]), "+f"(d[2]), "+f"(d[3])
        : "r"(a[0]), "r"(a[1]), "r"(a[2]), "r"(a[3]), "r"(b[0]), "r"(b[1]));
}
__device__ __forceinline__ void cpa16(uint32_t dst, const void* src) {
    asm volatile("cp.async.cg.shared.global [%0], [%1], 16;" :: "r"(dst), "l"(src));
}
#define CP_COMMIT() asm volatile("cp.async.commit_group;" ::: "memory")

__device__ __forceinline__ uint32_t pack_bf2(float a, float b) {
    return (uint32_t)__bfloat16_as_ushort(__float2bfloat16_rn(a)) |
           ((uint32_t)__bfloat16_as_ushort(__float2bfloat16_rn(b)) << 16);
}

// ---------------------------------------------------------------------------
// Row exp kernel: G = exp(v)/sqrt(rowsum) (bf16), sr = sqrt(rowsum) (fp32).
// Warp-per-row, fused over two tensors. No max-sub (x ~ N(0,1), exp safe).
// ---------------------------------------------------------------------------
__global__ void rowexp2_k(const float* __restrict__ in2, bf16* __restrict__ g2, float* __restrict__ sr2,
                          const float* __restrict__ in3, bf16* __restrict__ g3, float* __restrict__ sr3) {
    int gw = blockIdx.x * 8 + (threadIdx.x >> 5);
    int lane = threadIdx.x & 31;
    const int nrows = BB * NN;
    const float* in = (gw < nrows) ? in2 : in3;
    bf16* go = (gw < nrows) ? g2 : g3;
    float* so = (gw < nrows) ? sr2 : sr3;
    int row = (gw < nrows) ? gw : gw - nrows;

    const float* p = in + (size_t)row * DD;
    float e[6][4];
    float s = 0.0f;
    #pragma unroll
    for (int j = 0; j < 6; j++) {
        float4 v = *(const float4*)(p + (j * 32 + lane) * 4);
        e[j][0] = __expf(v.x); e[j][1] = __expf(v.y);
        e[j][2] = __expf(v.z); e[j][3] = __expf(v.w);
        s += (e[j][0] + e[j][1]) + (e[j][2] + e[j][3]);
    }
    #pragma unroll
    for (int off = 16; off; off >>= 1)
        s += __shfl_xor_sync(0xffffffffu, s, off);
    float sr = sqrtf(s);
    float inv = 1.0f / sr;
    if (lane == 0) so[row] = sr;

    bf16* gp = go + (size_t)row * DD;
    #pragma unroll
    for (int j = 0; j < 6; j++) {
        uint2 wg = make_uint2(pack_bf2(e[j][0] * inv, e[j][1] * inv),
                              pack_bf2(e[j][2] * inv, e[j][3] * inv));
        *(uint2*)(gp + (j * 32 + lane) * 4) = wg;
    }
}

// ---------------------------------------------------------------------------
// Column reduce: c[e] = sum_n G[n,e] * sr[n]  ->  1/c (fp32). Two tensors.
// ---------------------------------------------------------------------------
__global__ void colsum2_k(const bf16* __restrict__ g2, const float* __restrict__ sr2, float* __restrict__ c2i,
                          const bf16* __restrict__ g3, const float* __restrict__ sr3, float* __restrict__ c3i) {
    const bf16* G = blockIdx.z ? g3 : g2;
    const float* sr = blockIdx.z ? sr3 : sr2;
    float* ci = blockIdx.z ? c3i : c2i;
    int b = blockIdx.y;
    int dl = threadIdx.x & 31;
    int d = blockIdx.x * 32 + dl;
    int lane = threadIdx.x >> 5;

    const bf16* p = G + (size_t)b * NN * DD + d;
    const float* srb = sr + (size_t)b * NN;
    float s = 0.0f;
    for (int n = lane; n < NN; n += 8)
        s += __bfloat162float(p[(size_t)n * DD]) * srb[n];

    __shared__ float ss[8][32];
    ss[lane][dl] = s;
    __syncthreads();
    if (threadIdx.x < 32) {
        float S = ss[0][dl];
        #pragma unroll
        for (int i = 1; i < 8; i++) S += ss[i][dl];
        ci[(size_t)b * DD + d] = 1.0f / S;
    }
}

// ---------------------------------------------------------------------------
// Fused fp32 -> bf16 cast of W1, W2, x (one launch)
// ---------------------------------------------------------------------------
#define W4 (DD * DD / 4)
#define X4 (BB * NN * DD / 4)
__global__ void cast_all_k(const float* __restrict__ W1, const float* __restrict__ W2,
                           const float* __restrict__ x,
                           bf16* __restrict__ Wh, bf16* __restrict__ xh) {
    int i = blockIdx.x * blockDim.x + threadIdx.x;
    const float* src;
    bf16* dst;
    int j;
    if (i < W4)            { src = W1; dst = Wh;                 j = i; }
    else if (i < 2 * W4)   { src = W2; dst = Wh + (size_t)DD*DD; j = i - W4; }
    else if (i < 2*W4+X4)  { src = x;  dst = xh;                 j = i - 2 * W4; }
    else return;
    float4 v = ((const float4*)src)[j];
    ((uint2*)dst)[j] = make_uint2(pack_bf2(v.x, v.y), pack_bf2(v.z, v.w));
}

// ---------------------------------------------------------------------------
// Single-term bf16 GEMM (R11 core): C[m][n] = sum_k A[m][k] * B[n][k]
// CTA 128x128, K-TILE 64, 8 warps (warp 32x64), cp.async NSTG=3, 2 CTA/SM.
// mode 0: C -> bf16, optional per-column scale cinv[b*DD+col].
// mode 1: fp32 out = f*(acc+bias)+x.
// ---------------------------------------------------------------------------
#define ATILE  16384
#define STAGE  (2 * ATILE)
#define NSTG   3
#define SMEMSZ (NSTG * STAGE)

template <bool TR>
__global__ __launch_bounds__(256, 2)
void gemm1t_k(const bf16* __restrict__ Ah1, const bf16* __restrict__ Bh1, int kt1,
              const bf16* __restrict__ Ah2, const bf16* __restrict__ Bh2, int kt2,
              int dualz,
              long sA1, long sB1, long sA2, long sB2,
              int lda1, int ldb1, int lda2, int ldb2,
              int mode,
              float* __restrict__ Cf, bf16* __restrict__ Ch, bf16* __restrict__ Ch2,
              long sC, int ldc,
              const float* __restrict__ cinv1, const float* __restrict__ cinv2,
              const float* __restrict__ bias1, const float* __restrict__ bias2,
              const float* __restrict__ gate, const float* __restrict__ xres)
{
    extern __shared__ char sm[];
    uint32_t smb = smem_u32(sm);
    int tid = threadIdx.x, lane = tid & 31, wid = tid >> 5;
    int b = blockIdx.z, n0 = blockIdx.x * 128, m0 = blockIdx.y * 128;
    int wm = wid & 3, wn = wid >> 2;

    const bf16* A1p = Ah1;
    const bf16* B1p = Bh1;
    bf16* Chp = Ch;
    const float* cinvp = cinv1;
    if (dualz && b >= BB) { A1p = Ah2; B1p = Bh2; Chp = Ch2; cinvp = cinv2; b -= BB; }

    const bf16 *Ab1, *Bb1, *Ab2 = 0, *Bb2 = 0;
    if (TR) {
        Ab1 = A1p + (size_t)b * sA1 + m0;
        Bb1 = B1p + (size_t)b * sB1 + n0;
        if (!dualz && Ah2) { Ab2 = Ah2 + (size_t)b * sA2 + m0; Bb2 = Bh2 + (size_t)b * sB2 + n0; }
    } else {
        Ab1 = A1p + (size_t)b * sA1 + (size_t)m0 * lda1;
        Bb1 = B1p + (size_t)b * sB1 + (size_t)n0 * ldb1;
        if (!dualz && Ah2) { Ab2 = Ah2 + (size_t)b * sA2 + (size_t)m0 * lda2;
                             Bb2 = Bh2 + (size_t)b * sB2 + (size_t)n0 * ldb2; }
    }
    int KT = kt1 + kt2;

    #define ISSUE_STAGE(s) do {                                                          \
        int _s = (s);                                                                    \
        const bf16 *ah, *bh; int la, lb;                                                 \
        if (_s < kt1) { ah = Ab1; bh = Bb1; la = lda1; lb = ldb1; }                      \
        else { ah = Ab2; bh = Bb2; la = lda2; lb = ldb2; _s -= kt1; }                    \
        uint32_t sb = smb + (uint32_t)(((s) % NSTG)) * STAGE;                            \
        if (TR) {                                                                        \
            size_t kb = (size_t)_s * 64;                                                 \
            _Pragma("unroll")                                                            \
            for (int j = 0; j < 4; j++) {                                                \
                int q = tid + 256 * j;                                                   \
                int r = q >> 4, c = q & 15;                                              \
                uint32_t d = (uint32_t)r * 256 + ((uint32_t)(c ^ (r & 7)) << 4);         \
                cpa16(sb + d,         ah + (kb + r) * la + c * 8);                       \
                cpa16(sb + ATILE + d, bh + (kb + r) * lb + c * 8);                       \
            }                                                                            \
        } else {                                                                         \
            int ko = _s * 64;                                                            \
            _Pragma("unroll")                                                            \
            for (int j = 0; j < 4; j++) {                                                \
                int q = tid + 256 * j;                                                   \
                int r = q >> 3, c = q & 7;                                               \
                uint32_t d = (uint32_t)r * 128 + ((uint32_t)(c ^ (r & 7)) << 4);         \
                cpa16(sb + d,         ah + (size_t)r * la + ko + c * 8);                 \
                cpa16(sb + ATILE + d, bh + (size_t)r * lb + ko + c * 8);                 \
            }                                                                            \
        }                                                                                \
        CP_COMMIT();                                                                     \
    } while (0)

    // ldmatrix per-lane components
    int rA = 0, cAq = 0, swA = 0, rB = 0, cBq = 0, swB = 0;   // !TR
    int lrA = 0, chA0 = 0, lrB = 0, chB0 = 0, sx = 0;         // TR
    if (TR) {
        lrA  = (lane & 7) + ((lane >> 4) << 3);
        chA0 = wm * 4 + ((lane >> 3) & 1);
        lrB  = (lane & 7) + (((lane >> 3) & 1) << 3);
        chB0 = wn * 8 + ((lane >> 4) & 1);
        sx   = lane & 7;
    } else {
        rA  = wm * 32 + (lane & 7) + ((lane >> 3) & 1) * 8;
        cAq = lane >> 4;
        swA = rA & 7;
        rB  = wn * 64 + (lane & 7) + ((lane >> 4) & 1) * 8;
        cBq = (lane >> 3) & 1;
        swB = rB & 7;
    }

    float acc[2][8][4] = {};

    ISSUE_STAGE(0);
    ISSUE_STAGE(1);

    for (int kt = 0; kt < KT; kt++) {
        if (kt == KT - 1) asm volatile("cp.async.wait_group 0;" ::: "memory");
        else              asm volatile("cp.async.wait_group 1;" ::: "memory");
        __syncthreads();
        if (kt + 2 < KT) ISSUE_STAGE(kt + 2);

        uint32_t bA = smb + (uint32_t)(kt % NSTG) * STAGE;
        uint32_t bB = bA + ATILE;
        #pragma unroll
        for (int ks = 0; ks < 4; ks++) {
            uint32_t aH[2][4], bH[4][4];
            if (TR) {
                #pragma unroll
                for (int mi = 0; mi < 2; mi++)
                    ldsm4t(aH[mi], bA + (uint32_t)(lrA + ks * 16) * 256 +
                                   (uint32_t)(((chA0 + mi * 2) ^ sx) << 4));
                #pragma unroll
                for (int np = 0; np < 4; np++)
                    ldsm4t(bH[np], bB + (uint32_t)(lrB + ks * 16) * 256 +
                                   (uint32_t)(((chB0 + np * 2) ^ sx) << 4));
            } else {
                uint32_t offA = (uint32_t)rA * 128 + (uint32_t)(((ks * 2 + cAq) ^ swA) << 4);
                #pragma unroll
                for (int mi = 0; mi < 2; mi++)
                    ldsm4(aH[mi], bA + offA + mi * 2048);
                uint32_t offB = (uint32_t)rB * 128 + (uint32_t)(((ks * 2 + cBq) ^ swB) << 4);
                #pragma unroll
                for (int np = 0; np < 4; np++)
                    ldsm4(bH[np], bB + offB + np * 2048);
            }
            #pragma unroll
            for (int mi = 0; mi < 2; mi++)
                #pragma unroll
                for (int ni = 0; ni < 8; ni++)
                    mma16816(acc[mi][ni], aH[mi], &bH[ni >> 1][(ni & 1) * 2]);
        }
    }

    int g = lane >> 2, t4 = lane & 3;
    float f = 0.0f;
    if (mode == 1) f = 1.0f / (1.0f + __expf(-gate[0]));

    #pragma unroll
    for (int mi = 0; mi < 2; mi++) {
        #pragma unroll
        for (int ni = 0; ni < 8; ni++) {
            int row0 = m0 + wm * 32 + mi * 16 + g;
            int col = n0 + wn * 64 + ni * 8 + t4 * 2;
            if (mode == 0) {
                float cs0 = 1.0f, cs1 = 1.0f;
                if (cinvp) {
                    cs0 = cinvp[(size_t)b * DD + col];
                    cs1 = cinvp[(size_t)b * DD + col + 1];
                }
                size_t i0 = (size_t)b * sC + (size_t)row0 * ldc + col;
                size_t i1 = i0 + (size_t)8 * ldc;
                *(uint32_t*)(Chp + i0) = pack_bf2(acc[mi][ni][0] * cs0, acc[mi][ni][1] * cs1);
                *(uint32_t*)(Chp + i1) = pack_bf2(acc[mi][ni][2] * cs0, acc[mi][ni][3] * cs1);
            } else {
                float g1 = bias1[col] + bias2[col];
                float g2 = bias1[col + 1] + bias2[col + 1];
                const float* x0 = xres + (size_t)b * NN * DD + (size_t)row0 * DD + col;
                const float* x1 = x0 + (size_t)8 * DD;
                float2 xv0 = *(const float2*)x0;
                float2 xv1 = *(const float2*)x1;
                float* p0 = Cf + (size_t)b * sC + (size_t)row0 * ldc + col;
                float* p1 = p0 + (size_t)8 * ldc;
                *(float2*)p0 = make_float2(f * (acc[mi][ni][0] + g1) + xv0.x,
                                           f * (acc[mi][ni][1] + g2) + xv0.y);
                *(float2*)p1 = make_float2(f * (acc[mi][ni][2] + g1) + xv1.x,
                                           f * (acc[mi][ni][3] + g2) + xv1.y);
            }
        }
    }
    #undef ISSUE_STAGE
}

// ---------------------------------------------------------------------------
extern "C" void kernel_launch(void* const* d_in, const int* in_sizes, int n_in,
                              void* d_out, int out_size) {
    const float* x  = (const float*)d_in[0];
    const float* x2 = (const float*)d_in[1];
    const float* x3 = (const float*)d_in[2];
    const float* W1 = (const float*)d_in[3];
    const float* b1 = (const float*)d_in[4];
    const float* W2 = (const float*)d_in[5];
    const float* b2 = (const float*)d_in[6];
    const float* w  = (const float*)d_in[7];
    float* out = (float*)d_out;

    bf16 *G2h, *G3h, *S1h, *S2h, *MTh, *Wh, *xh;
    float *sr2, *sr3, *c2i, *c3i;
    cudaGetSymbolAddress((void**)&G2h, g_G2h);
    cudaGetSymbolAddress((void**)&G3h, g_G3h);
    cudaGetSymbolAddress((void**)&sr2, g_sr2);
    cudaGetSymbolAddress((void**)&sr3, g_sr3);
    cudaGetSymbolAddress((void**)&c2i, g_c2i);
    cudaGetSymbolAddress((void**)&c3i, g_c3i);
    cudaGetSymbolAddress((void**)&S1h, g_S1h);
    cudaGetSymbolAddress((void**)&S2h, g_S2h);
    cudaGetSymbolAddress((void**)&MTh, g_MTh);
    cudaGetSymbolAddress((void**)&Wh,  g_Wh);
    cudaGetSymbolAddress((void**)&xh,  g_xh);

    cudaFuncSetAttribute(gemm1t_k<true>,  cudaFuncAttributeMaxDynamicSharedMemorySize, SMEMSZ);
    cudaFuncSetAttribute(gemm1t_k<false>, cudaFuncAttributeMaxDynamicSharedMemorySize, SMEMSZ);

    long sTok = (long)NN * DD;
    long sDD  = (long)DD * DD;

    // 1) fused bf16 casts (W1, W2, x)
    cast_all_k<<<(2 * W4 + X4 + 255) / 256, 256>>>(W1, W2, x, Wh, xh);

    // 2) fused row-exp: G = exp/sqrt(rowsum), sr = sqrt(rowsum)
    rowexp2_k<<<2 * BB * NN / 8, 256>>>(x2, G2h, sr2, x3, G3h, sr3);

    // 3) column reduce: 1/c[e] = 1 / sum_n G[n,e]*sr[n]
    colsum2_k<<<dim3(DD / 32, BB, 2), 256>>>(G2h, sr2, c2i, G3h, sr3, c3i);

    // 4) attention GEMMs: S = (G^T G) * diag(1/c), full grid (TR path, dualz)
    gemm1t_k<true><<<dim3(DD / 128, DD / 128, 2 * BB), 256, SMEMSZ>>>(
        G2h, G2h, NN / 64, G3h, G3h, 0, /*dualz=*/1,
        sTok, sTok, sTok, sTok, DD, DD, DD, DD,
        0, nullptr, S1h, S2h, sDD, DD,
        c2i, c3i, nullptr, nullptr, nullptr, nullptr);

    // 5) MT[e][d] = sum_k W1[e][k]*S1[d][k] + W2[e][k]*S2[d][k]
    gemm1t_k<false><<<dim3(DD / 128, DD / 128, BB), 256, SMEMSZ>>>(
        Wh, S1h, DD / 64, Wh + (size_t)DD * DD, S2h, DD / 64, /*dualz=*/0,
        0, sDD, 0, sDD, DD, DD, DD, DD,
        0, nullptr, MTh, nullptr, sDD, DD,
        nullptr, nullptr, nullptr, nullptr, nullptr, nullptr);

    // 6) out[n][e] = f*( sum_d x[n][d]*MT[e][d] + b1[e]+b2[e] ) + x[n][e]
    gemm1t_k<false><<<dim3(DD / 128, NN / 128, BB), 256, SMEMSZ>>>(
        xh, MTh, DD / 64, nullptr, nullptr, 0, /*dualz=*/0,
        sTok, sDD, 0, 0, DD, DD, 0, 0,
        1, out, nullptr, nullptr, sTok, DD,
        nullptr, nullptr, b1, b2, w, x);
}

// round 15
// speedup vs baseline: 1.1107x; 1.1107x over previous
#include <cuda_runtime.h>
#include <cuda_bf16.h>
#include <cstdint>
#include <math.h>

#define BB 8
#define NN 2048
#define DD 768

typedef __nv_bfloat16 bf16;

// ---------------- scratch (no allocation allowed) ----------------
__device__ bf16 g_K2h[BB * NN * DD];   // row-softmax(x2)
__device__ bf16 g_E2h[BB * NN * DD];   // exp(x2)
__device__ bf16 g_K3h[BB * NN * DD];
__device__ bf16 g_E3h[BB * NN * DD];
__device__ float g_c2i[BB * DD];       // 1 / colsum(exp(x2))
__device__ float g_c3i[BB * DD];
__device__ bf16 g_S1h[BB * DD * DD];
__device__ bf16 g_S2h[BB * DD * DD];
__device__ bf16 g_MTh[BB * DD * DD];
__device__ bf16 g_Wh [2 * DD * DD];
__device__ bf16 g_xh [BB * NN * DD];

// ---------------- helpers ----------------
__device__ __forceinline__ uint32_t smem_u32(const void* p) {
    uint32_t a;
    asm("{ .reg .u64 t; cvta.to.shared.u64 t, %1; cvt.u32.u64 %0, t; }" : "=r"(a) : "l"(p));
    return a;
}
__device__ __forceinline__ void ldsm4(uint32_t* r, uint32_t addr) {
    asm volatile("ldmatrix.sync.aligned.m8n8.x4.shared.b16 {%0,%1,%2,%3}, [%4];"
        : "=r"(r[0]), "=r"(r[1]), "=r"(r[2]), "=r"(r[3]) : "r"(addr));
}
__device__ __forceinline__ void ldsm4t(uint32_t* r, uint32_t addr) {
    asm volatile("ldmatrix.sync.aligned.m8n8.x4.trans.shared.b16 {%0,%1,%2,%3}, [%4];"
        : "=r"(r[0]), "=r"(r[1]), "=r"(r[2]), "=r"(r[3]) : "r"(addr));
}
__device__ __forceinline__ void mma16816(float* d, const uint32_t* a, const uint32_t* b) {
    asm volatile("mma.sync.aligned.m16n8k16.row.col.f32.bf16.bf16.f32 "
        "{%0,%1,%2,%3}, {%4,%5,%6,%7}, {%8,%9}, {%0,%1,%2,%3};"
        : "+f"(d[0]), "+f"(d[1]), "+f"(d[2]), "+f"(d[3])
        : "r"(a[0]), "r"(a[1]), "r"(a[2]), "r"(a[3]), "r"(b[0]), "r"(b[1]));
}
__device__ __forceinline__ void cpa16(uint32_t dst, const void* src) {
    asm volatile("cp.async.cg.shared.global [%0], [%1], 16;" :: "r"(dst), "l"(src));
}
#define CP_COMMIT() asm volatile("cp.async.commit_group;" ::: "memory")

__device__ __forceinline__ uint32_t pack_bf2(float a, float b) {
    return (uint32_t)__bfloat16_as_ushort(__float2bfloat16_rn(a)) |
           ((uint32_t)__bfloat16_as_ushort(__float2bfloat16_rn(b)) << 16);
}

// ---------------------------------------------------------------------------
// Row exp kernel: E = exp(v) (bf16) and K' = exp(v)/rowsum (bf16).
// Warp-per-row, fused over two tensors. No max-sub (x ~ N(0,1), exp safe).
// ---------------------------------------------------------------------------
__global__ void rowexp2_k(const float* __restrict__ in2, bf16* __restrict__ k2, bf16* __restrict__ e2,
                          const float* __restrict__ in3, bf16* __restrict__ k3, bf16* __restrict__ e3) {
    int gw = blockIdx.x * 8 + (threadIdx.x >> 5);
    int lane = threadIdx.x & 31;
    const int nrows = BB * NN;
    const float* in = (gw < nrows) ? in2 : in3;
    bf16* ko = (gw < nrows) ? k2 : k3;
    bf16* eo = (gw < nrows) ? e2 : e3;
    int row = (gw < nrows) ? gw : gw - nrows;

    const float* p = in + (size_t)row * DD;
    float e[6][4];
    float s = 0.0f;
    #pragma unroll
    for (int j = 0; j < 6; j++) {
        float4 v = *(const float4*)(p + (j * 32 + lane) * 4);
        e[j][0] = __expf(v.x); e[j][1] = __expf(v.y);
        e[j][2] = __expf(v.z); e[j][3] = __expf(v.w);
        s += (e[j][0] + e[j][1]) + (e[j][2] + e[j][3]);
    }
    #pragma unroll
    for (int off = 16; off; off >>= 1)
        s += __shfl_xor_sync(0xffffffffu, s, off);
    float inv = 1.0f / s;

    bf16* kp = ko + (size_t)row * DD;
    bf16* ep = eo + (size_t)row * DD;
    #pragma unroll
    for (int j = 0; j < 6; j++) {
        uint2 we = make_uint2(pack_bf2(e[j][0], e[j][1]), pack_bf2(e[j][2], e[j][3]));
        uint2 wk = make_uint2(pack_bf2(e[j][0] * inv, e[j][1] * inv),
                              pack_bf2(e[j][2] * inv, e[j][3] * inv));
        *(uint2*)(ep + (j * 32 + lane) * 4) = we;
        *(uint2*)(kp + (j * 32 + lane) * 4) = wk;
    }
}

// ---------------------------------------------------------------------------
// Column-sum of bf16 E over tokens -> 1/c (fp32). Fused over two tensors.
// ---------------------------------------------------------------------------
__global__ void colsum2_k(const bf16* __restrict__ e2, float* __restrict__ c2i,
                          const bf16* __restrict__ e3, float* __restrict__ c3i) {
    const bf16* E = blockIdx.z ? e3 : e2;
    float* ci = blockIdx.z ? c3i : c2i;
    int b = blockIdx.y;
    int dl = threadIdx.x & 31;
    int d = blockIdx.x * 32 + dl;
    int lane = threadIdx.x >> 5;

    const bf16* p = E + (size_t)b * NN * DD + d;
    float s = 0.0f;
    for (int n = lane; n < NN; n += 8)
        s += __bfloat162float(p[(size_t)n * DD]);

    __shared__ float ss[8][32];
    ss[lane][dl] = s;
    __syncthreads();
    if (threadIdx.x < 32) {
        float S = ss[0][dl];
        #pragma unroll
        for (int i = 1; i < 8; i++) S += ss[i][dl];
        ci[(size_t)b * DD + d] = 1.0f / S;
    }
}

// ---------------------------------------------------------------------------
// Fused fp32 -> bf16 cast of W1, W2, x (one launch, runs on side stream)
// ---------------------------------------------------------------------------
#define W4 (DD * DD / 4)
#define X4 (BB * NN * DD / 4)
__global__ void cast_all_k(const float* __restrict__ W1, const float* __restrict__ W2,
                           const float* __restrict__ x,
                           bf16* __restrict__ Wh, bf16* __restrict__ xh) {
    int i = blockIdx.x * blockDim.x + threadIdx.x;
    const float* src;
    bf16* dst;
    int j;
    if (i < W4)            { src = W1; dst = Wh;                 j = i; }
    else if (i < 2 * W4)   { src = W2; dst = Wh + (size_t)DD*DD; j = i - W4; }
    else if (i < 2*W4+X4)  { src = x;  dst = xh;                 j = i - 2 * W4; }
    else return;
    float4 v = ((const float4*)src)[j];
    ((uint2*)dst)[j] = make_uint2(pack_bf2(v.x, v.y), pack_bf2(v.z, v.w));
}

// ---------------------------------------------------------------------------
// Single-term bf16 GEMM (R11 core): C[m][n] = sum_k A[m][k] * B[n][k]
// CTA 128x128, K-TILE 64, 8 warps (warp 32x64), cp.async NSTG=3, 2 CTA/SM.
// mode 0: C -> bf16, optional per-column scale cinv[b*DD+col].
// mode 1: fp32 out = f*(acc+bias)+x.
// ---------------------------------------------------------------------------
#define ATILE  16384
#define STAGE  (2 * ATILE)
#define NSTG   3
#define SMEMSZ (NSTG * STAGE)

template <bool TR>
__global__ __launch_bounds__(256, 2)
void gemm1t_k(const bf16* __restrict__ Ah1, const bf16* __restrict__ Bh1, int kt1,
              const bf16* __restrict__ Ah2, const bf16* __restrict__ Bh2, int kt2,
              int dualz,
              long sA1, long sB1, long sA2, long sB2,
              int lda1, int ldb1, int lda2, int ldb2,
              int mode,
              float* __restrict__ Cf, bf16* __restrict__ Ch, bf16* __restrict__ Ch2,
              long sC, int ldc,
              const float* __restrict__ cinv1, const float* __restrict__ cinv2,
              const float* __restrict__ bias1, const float* __restrict__ bias2,
              const float* __restrict__ gate, const float* __restrict__ xres)
{
    extern __shared__ char sm[];
    uint32_t smb = smem_u32(sm);
    int tid = threadIdx.x, lane = tid & 31, wid = tid >> 5;
    int b = blockIdx.z, n0 = blockIdx.x * 128, m0 = blockIdx.y * 128;
    int wm = wid & 3, wn = wid >> 2;

    const bf16* A1p = Ah1;
    const bf16* B1p = Bh1;
    bf16* Chp = Ch;
    const float* cinvp = cinv1;
    if (dualz && b >= BB) { A1p = Ah2; B1p = Bh2; Chp = Ch2; cinvp = cinv2; b -= BB; }

    const bf16 *Ab1, *Bb1, *Ab2 = 0, *Bb2 = 0;
    if (TR) {
        Ab1 = A1p + (size_t)b * sA1 + m0;
        Bb1 = B1p + (size_t)b * sB1 + n0;
        if (!dualz && Ah2) { Ab2 = Ah2 + (size_t)b * sA2 + m0; Bb2 = Bh2 + (size_t)b * sB2 + n0; }
    } else {
        Ab1 = A1p + (size_t)b * sA1 + (size_t)m0 * lda1;
        Bb1 = B1p + (size_t)b * sB1 + (size_t)n0 * ldb1;
        if (!dualz && Ah2) { Ab2 = Ah2 + (size_t)b * sA2 + (size_t)m0 * lda2;
                             Bb2 = Bh2 + (size_t)b * sB2 + (size_t)n0 * ldb2; }
    }
    int KT = kt1 + kt2;

    #define ISSUE_STAGE(s) do {                                                          \
        int _s = (s);                                                                    \
        const bf16 *ah, *bh; int la, lb;                                                 \
        if (_s < kt1) { ah = Ab1; bh = Bb1; la = lda1; lb = ldb1; }                      \
        else { ah = Ab2; bh = Bb2; la = lda2; lb = ldb2; _s -= kt1; }                    \
        uint32_t sb = smb + (uint32_t)(((s) % NSTG)) * STAGE;                            \
        if (TR) {                                                                        \
            size_t kb = (size_t)_s * 64;                                                 \
            _Pragma("unroll")                                                            \
            for (int j = 0; j < 4; j++) {                                                \
                int q = tid + 256 * j;                                                   \
                int r = q >> 4, c = q & 15;                                              \
                uint32_t d = (uint32_t)r * 256 + ((uint32_t)(c ^ (r & 7)) << 4);         \
                cpa16(sb + d,         ah + (kb + r) * la + c * 8);                       \
                cpa16(sb + ATILE + d, bh + (kb + r) * lb + c * 8);                       \
            }                                                                            \
        } else {                                                                         \
            int ko = _s * 64;                                                            \
            _Pragma("unroll")                                                            \
            for (int j = 0; j < 4; j++) {                                                \
                int q = tid + 256 * j;                                                   \
                int r = q >> 3, c = q & 7;                                               \
                uint32_t d = (uint32_t)r * 128 + ((uint32_t)(c ^ (r & 7)) << 4);         \
                cpa16(sb + d,         ah + (size_t)r * la + ko + c * 8);                 \
                cpa16(sb + ATILE + d, bh + (size_t)r * lb + ko + c * 8);                 \
            }                                                                            \
        }                                                                                \
        CP_COMMIT();                                                                     \
    } while (0)

    // ldmatrix per-lane components
    int rA = 0, cAq = 0, swA = 0, rB = 0, cBq = 0, swB = 0;   // !TR
    int lrA = 0, chA0 = 0, lrB = 0, chB0 = 0, sx = 0;         // TR
    if (TR) {
        lrA  = (lane & 7) + ((lane >> 4) << 3);
        chA0 = wm * 4 + ((lane >> 3) & 1);
        lrB  = (lane & 7) + (((lane >> 3) & 1) << 3);
        chB0 = wn * 8 + ((lane >> 4) & 1);
        sx   = lane & 7;
    } else {
        rA  = wm * 32 + (lane & 7) + ((lane >> 3) & 1) * 8;
        cAq = lane >> 4;
        swA = rA & 7;
        rB  = wn * 64 + (lane & 7) + ((lane >> 4) & 1) * 8;
        cBq = (lane >> 3) & 1;
        swB = rB & 7;
    }

    float acc[2][8][4] = {};

    ISSUE_STAGE(0);
    ISSUE_STAGE(1);

    for (int kt = 0; kt < KT; kt++) {
        if (kt == KT - 1) asm volatile("cp.async.wait_group 0;" ::: "memory");
        else              asm volatile("cp.async.wait_group 1;" ::: "memory");
        __syncthreads();
        if (kt + 2 < KT) ISSUE_STAGE(kt + 2);

        uint32_t bA = smb + (uint32_t)(kt % NSTG) * STAGE;
        uint32_t bB = bA + ATILE;
        #pragma unroll
        for (int ks = 0; ks < 4; ks++) {
            uint32_t aH[2][4], bH[4][4];
            if (TR) {
                #pragma unroll
                for (int mi = 0; mi < 2; mi++)
                    ldsm4t(aH[mi], bA + (uint32_t)(lrA + ks * 16) * 256 +
                                   (uint32_t)(((chA0 + mi * 2) ^ sx) << 4));
                #pragma unroll
                for (int np = 0; np < 4; np++)
                    ldsm4t(bH[np], bB + (uint32_t)(lrB + ks * 16) * 256 +
                                   (uint32_t)(((chB0 + np * 2) ^ sx) << 4));
            } else {
                uint32_t offA = (uint32_t)rA * 128 + (uint32_t)(((ks * 2 + cAq) ^ swA) << 4);
                #pragma unroll
                for (int mi = 0; mi < 2; mi++)
                    ldsm4(aH[mi], bA + offA + mi * 2048);
                uint32_t offB = (uint32_t)rB * 128 + (uint32_t)(((ks * 2 + cBq) ^ swB) << 4);
                #pragma unroll
                for (int np = 0; np < 4; np++)
                    ldsm4(bH[np], bB + offB + np * 2048);
            }
            #pragma unroll
            for (int mi = 0; mi < 2; mi++)
                #pragma unroll
                for (int ni = 0; ni < 8; ni++)
                    mma16816(acc[mi][ni], aH[mi], &bH[ni >> 1][(ni & 1) * 2]);
        }
    }

    int g = lane >> 2, t4 = lane & 3;
    float f = 0.0f;
    if (mode == 1) f = 1.0f / (1.0f + __expf(-gate[0]));

    #pragma unroll
    for (int mi = 0; mi < 2; mi++) {
        #pragma unroll
        for (int ni = 0; ni < 8; ni++) {
            int row0 = m0 + wm * 32 + mi * 16 + g;
            int col = n0 + wn * 64 + ni * 8 + t4 * 2;
            if (mode == 0) {
                float cs0 = 1.0f, cs1 = 1.0f;
                if (cinvp) {
                    cs0 = cinvp[(size_t)b * DD + col];
                    cs1 = cinvp[(size_t)b * DD + col + 1];
                }
                size_t i0 = (size_t)b * sC + (size_t)row0 * ldc + col;
                size_t i1 = i0 + (size_t)8 * ldc;
                *(uint32_t*)(Chp + i0) = pack_bf2(acc[mi][ni][0] * cs0, acc[mi][ni][1] * cs1);
                *(uint32_t*)(Chp + i1) = pack_bf2(acc[mi][ni][2] * cs0, acc[mi][ni][3] * cs1);
            } else {
                float g1 = bias1[col] + bias2[col];
                float g2 = bias1[col + 1] + bias2[col + 1];
                const float* x0 = xres + (size_t)b * NN * DD + (size_t)row0 * DD + col;
                const float* x1 = x0 + (size_t)8 * DD;
                float2 xv0 = *(const float2*)x0;
                float2 xv1 = *(const float2*)x1;
                float* p0 = Cf + (size_t)b * sC + (size_t)row0 * ldc + col;
                float* p1 = p0 + (size_t)8 * ldc;
                *(float2*)p0 = make_float2(f * (acc[mi][ni][0] + g1) + xv0.x,
                                           f * (acc[mi][ni][1] + g2) + xv0.y);
                *(float2*)p1 = make_float2(f * (acc[mi][ni][2] + g1) + xv1.x,
                                           f * (acc[mi][ni][3] + g2) + xv1.y);
            }
        }
    }
    #undef ISSUE_STAGE
}

// ---------------------------------------------------------------------------
extern "C" void kernel_launch(void* const* d_in, const int* in_sizes, int n_in,
                              void* d_out, int out_size) {
    const float* x  = (const float*)d_in[0];
    const float* x2 = (const float*)d_in[1];
    const float* x3 = (const float*)d_in[2];
    const float* W1 = (const float*)d_in[3];
    const float* b1 = (const float*)d_in[4];
    const float* W2 = (const float*)d_in[5];
    const float* b2 = (const float*)d_in[6];
    const float* w  = (const float*)d_in[7];
    float* out = (float*)d_out;

    bf16 *K2h, *E2h, *K3h, *E3h, *S1h, *S2h, *MTh, *Wh, *xh;
    float *c2i, *c3i;
    cudaGetSymbolAddress((void**)&K2h, g_K2h);
    cudaGetSymbolAddress((void**)&E2h, g_E2h);
    cudaGetSymbolAddress((void**)&K3h, g_K3h);
    cudaGetSymbolAddress((void**)&E3h, g_E3h);
    cudaGetSymbolAddress((void**)&c2i, g_c2i);
    cudaGetSymbolAddress((void**)&c3i, g_c3i);
    cudaGetSymbolAddress((void**)&S1h, g_S1h);
    cudaGetSymbolAddress((void**)&S2h, g_S2h);
    cudaGetSymbolAddress((void**)&MTh, g_MTh);
    cudaGetSymbolAddress((void**)&Wh,  g_Wh);
    cudaGetSymbolAddress((void**)&xh,  g_xh);

    cudaFuncSetAttribute(gemm1t_k<true>,  cudaFuncAttributeMaxDynamicSharedMemorySize, SMEMSZ);
    cudaFuncSetAttribute(gemm1t_k<false>, cudaFuncAttributeMaxDynamicSharedMemorySize, SMEMSZ);

    // side stream + events for the independent cast (created once; host-side
    // objects only, no device memory)
    static cudaStream_t s2 = nullptr;
    static cudaEvent_t evFork = nullptr, evJoin = nullptr;
    if (!s2) {
        cudaStreamCreateWithFlags(&s2, cudaStreamNonBlocking);
        cudaEventCreateWithFlags(&evFork, cudaEventDisableTiming);
        cudaEventCreateWithFlags(&evJoin, cudaEventDisableTiming);
    }

    long sTok = (long)NN * DD;
    long sDD  = (long)DD * DD;

    // 1) fork: fused bf16 casts (W1, W2, x) on side stream, overlapped with 2-4
    cudaEventRecord(evFork, 0);
    cudaStreamWaitEvent(s2, evFork, 0);
    cast_all_k<<<(2 * W4 + X4 + 255) / 256, 256, 0, s2>>>(W1, W2, x, Wh, xh);
    cudaEventRecord(evJoin, s2);

    // 2) fused row softmax+exp: K' = exp/rowsum, E = exp (both tensors)
    rowexp2_k<<<2 * BB * NN / 8, 256>>>(x2, K2h, E2h, x3, K3h, E3h);

    // 3) column sums of E -> 1/c (both tensors)
    colsum2_k<<<dim3(DD / 32, BB, 2), 256>>>(E2h, c2i, E3h, c3i);

    // 4) fused attention GEMMs: S = (K'^T @ E) * (1/c[col])  (TR path, dualz)
    gemm1t_k<true><<<dim3(DD / 128, DD / 128, 2 * BB), 256, SMEMSZ>>>(
        K2h, E2h, NN / 64, K3h, E3h, 0, /*dualz=*/1,
        sTok, sTok, sTok, sTok, DD, DD, DD, DD,
        0, nullptr, S1h, S2h, sDD, DD,
        c2i, c3i, nullptr, nullptr, nullptr, nullptr);

    // join: GEMM5 needs Wh (and GEMM6 needs xh)
    cudaStreamWaitEvent(0, evJoin, 0);

    // 5) MT[e][d] = sum_k W1[e][k]*S1[d][k] + W2[e][k]*S2[d][k]
    gemm1t_k<false><<<dim3(DD / 128, DD / 128, BB), 256, SMEMSZ>>>(
        Wh, S1h, DD / 64, Wh + (size_t)DD * DD, S2h, DD / 64, /*dualz=*/0,
        0, sDD, 0, sDD, DD, DD, DD, DD,
        0, nullptr, MTh, nullptr, sDD, DD,
        nullptr, nullptr, nullptr, nullptr, nullptr, nullptr);

    // 6) out[n][e] = f*( sum_d x[n][d]*MT[e][d] + b1[e]+b2[e] ) + x[n][e]
    gemm1t_k<false><<<dim3(DD / 128, NN / 128, BB), 256, SMEMSZ>>>(
        xh, MTh, DD / 64, nullptr, nullptr, 0, /*dualz=*/0,
        sTok, sDD, 0, 0, DD, DD, 0, 0,
        1, out, nullptr, nullptr, sTok, DD,
        nullptr, nullptr, b1, b2, w, x);
}